// round 8
// baseline (speedup 1.0000x reference)
#include <cuda_runtime.h>
#include <stdint.h>

// Problem constants (fixed by the reference: NX=41, r_max=6.0, voxel=0.3, K=4, min_sep=3)
#define NXG    41
#define NROWS  (NXG * NXG)       // 1681 rows of 41 voxels
#define GVOX   (NXG * NXG * NXG) // 68921
#define KP     4
#define SEP    3
#define NEGF   (-1.0e9f)
#define VTH    (-1.0e8f)

#define THREADS 256
#define NWARP   8
#define WCH     16                            // rows per warp-chunk
#define WBUF    (WCH * NXG + 8)               // 664 floats; 2656 B, multiple of 16

// Shared-memory layout (bytes); buffer base 16B-aligned, WBUF*4 mult of 16.
#define SM_BUF    0                                   // 8*2*664*4 = 42496
#define SM_MBAR   (SM_BUF + NWARP * 2 * WBUF * 4)     // 128
#define SM_ROWMAX (SM_MBAR + 128)                     // 6724
#define SM_ROWLO  (SM_ROWMAX + NROWS * 4)             // 1684
#define SM_XS2    (SM_ROWLO + 1684)                   // 168
#define SM_YS2    (SM_XS2 + 168)
#define SM_ZZ     (SM_YS2 + 168)
#define SM_SWV    (SM_ZZ + 168)
#define SM_SWR    (SM_SWV + 32)
#define SM_PICK   (SM_SWR + 32)
#define SM_PKK    (SM_PICK + 4)
#define SM_PS     (SM_PKK + 4)
#define SM_PG     (SM_PS + 16)
#define SM_PV     (SM_PG + 16)
#define SM_TOTAL  (SM_PV + 16 + 32)                   // ~51.7 KB -> 4 CTAs/SM

#define CP_ASYNC_4(dst, src) \
    asm volatile("cp.async.ca.shared.global [%0], [%1], 4;"  :: "r"(dst), "l"(src) : "memory")
#define CP_COMMIT()  asm volatile("cp.async.commit_group;" ::: "memory")
#define CP_WAIT0()   asm volatile("cp.async.wait_group 0;" ::: "memory")

#define MBAR_INIT(mbar, cnt) \
    asm volatile("mbarrier.init.shared.b64 [%0], %1;" :: "r"(mbar), "r"(cnt) : "memory")
#define MBAR_EXPECT_TX(mbar, bytes) \
    asm volatile("mbarrier.arrive.expect_tx.shared.b64 _, [%0], %1;" :: "r"(mbar), "r"(bytes) : "memory")
#define FENCE_PROXY_ASYNC() asm volatile("fence.proxy.async.shared::cta;" ::: "memory")

#define MBAR_WAIT(mbar, par) do {                                              \
    uint32_t _m = (mbar); uint32_t _p = (par); uint32_t _d;                    \
    asm volatile("{\n\t.reg .pred p;\n\t"                                      \
        "mbarrier.try_wait.parity.acquire.cta.shared::cta.b64 p, [%1], %2;\n\t"\
        "selp.b32 %0, 1, 0, p;\n\t}"                                           \
        : "=r"(_d) : "r"(_m), "r"(_p) : "memory");                             \
    if (!_d) {                                                                 \
        asm volatile("{\n\t.reg .pred P1;\n\t"                                 \
            "WL_%=:\n\t"                                                       \
            "mbarrier.try_wait.parity.acquire.cta.shared::cta.b64 P1, [%0], %1, 0x989680;\n\t" \
            "@P1 bra.uni WD_%=;\n\t"                                           \
            "bra.uni WL_%=;\n\t"                                               \
            "WD_%=:\n\t}"                                                      \
            :: "r"(_m), "r"(_p) : "memory");                                   \
    }                                                                          \
} while (0)

#define BULK_LD(dst, src, bytes, mbar) \
    asm volatile("cp.async.bulk.shared::cluster.global.mbarrier::complete_tx::bytes " \
                 "[%0], [%1], %2, [%3];" \
                 :: "r"(dst), "l"(src), "r"(bytes), "r"(mbar) : "memory")

static __device__ __forceinline__ uint32_t smem_u32(const void* p) {
    return (uint32_t)__cvta_generic_to_shared(p);
}

// Exact floor(r/41) for 0 <= r < 53773.
static __device__ __forceinline__ int div41(int r) {
    return (int)(((unsigned)r * 51151u) >> 21);
}

// ---------------------------------------------------------------------------
// Fully fused: TMA-bulk double-buffered streaming; phase-1 computes per-row
// MAX VALUE only (interval mask, no index tracking); picked-row argmax-k is
// recomputed on demand in phase 2. One CTA per (n,c) problem.
__global__ __launch_bounds__(THREADS, 4)
void fused_peaks_kernel(const float* __restrict__ density,
                        const float* __restrict__ grid_xyz,
                        const float* __restrict__ Rmats,
                        const float* __restrict__ tpos,
                        const float* __restrict__ node_mask,
                        float* __restrict__ out,
                        int C)
{
    extern __shared__ char smem[];
    float*   bufs   = (float*)(smem + SM_BUF);
    float*   rowmax = (float*)(smem + SM_ROWMAX);
    uint8_t* rowlo  = (uint8_t*)(smem + SM_ROWLO);
    float*   xs2    = (float*)(smem + SM_XS2);
    float*   ys2    = (float*)(smem + SM_YS2);
    float*   zz     = (float*)(smem + SM_ZZ);
    float*   swv    = (float*)(smem + SM_SWV);
    int*     swr    = (int*)(smem + SM_SWR);
    int*     s_pick = (int*)(smem + SM_PICK);
    int*     s_pkk  = (int*)(smem + SM_PKK);
    float*   s_ps   = (float*)(smem + SM_PS);
    int*     s_pg   = (int*)(smem + SM_PG);
    int*     s_pv   = (int*)(smem + SM_PV);

    const int tid  = threadIdx.x;
    const int lane = tid & 31;
    const int w    = tid >> 5;
    const int p    = blockIdx.x;
    const size_t base    = (size_t)p * GVOX;        // base % 4 == p % 4
    const size_t total_f = (size_t)gridDim.x * GVOX;

    // Warp-private row range, buffers, mbarriers (one per stage).
    const int rstart = (w * NROWS) >> 3;
    const int rend   = ((w + 1) * NROWS) >> 3;
    const int nch    = (rend - rstart + WCH - 1) / WCH;
    float* wb[2] = { bufs + (w * 2 + 0) * WBUF, bufs + (w * 2 + 1) * WBUF };
    const uint32_t mb0 = smem_u32(smem + SM_MBAR) + (uint32_t)w * 16u;

    if (lane == 0) { MBAR_INIT(mb0, 1); MBAR_INIT(mb0 + 8, 1); }
    __syncwarp();
    FENCE_PROXY_ASYNC();

    int tailflag = 0;   // set iff a rare cp.async tail was used (uniform per warp)

    auto issue_chunk = [&](int c) {
        const int row0  = rstart + c * WCH;
        const int nrows = min(WCH, rend - row0);
        const size_t need_start = base + (size_t)row0 * NXG;
        const size_t srcA = need_start & ~(size_t)3;          // 16B-aligned float idx
        size_t endA = (need_start + (size_t)nrows * NXG + 3) & ~(size_t)3;
        int tail = 0;
        if (endA > total_f) { endA -= 4; tail = 1; }          // never for NC%4==0
        const uint32_t bytes = (uint32_t)(endA - srcA) * 4u;
        const uint32_t dstb  = smem_u32(wb[c & 1]);
        const uint32_t mbar  = mb0 + (uint32_t)(c & 1) * 8u;
        if (lane == 0) {
            MBAR_EXPECT_TX(mbar, bytes);
            BULK_LD(dstb, density + srcA, bytes, mbar);
        }
        if (tail) {
            const size_t need_end = need_start + (size_t)nrows * NXG;
            const int nrem = (int)(need_end - endA);          // 1..4
            if (lane < nrem)
                CP_ASYNC_4(dstb + (uint32_t)(endA - srcA + lane) * 4u,
                           density + endA + lane);
            CP_COMMIT();
            tailflag = 1;
        }
    };

    issue_chunk(0);    // overlaps table building below

    // Per-axis squared coords from the ACTUAL grid_xyz input.
    // Sphere test (s<=36.0f) is bit-equivalent to sqrtf(s)<=6.0f under RN.
    if (tid < NXG) {
        float x = grid_xyz[3 * (tid * NXG * NXG) + 0];
        float y = grid_xyz[3 * (tid * NXG) + 1];
        float z = grid_xyz[3 * tid + 2];
        xs2[tid] = __fmul_rn(x, x);
        ys2[tid] = __fmul_rn(y, y);
        zz[tid]  = __fmul_rn(z, z);
    }
    __syncthreads();

    // Per-row valid interval: valid ks = [klo, 40-klo], klo = 20-d where
    // d = max{d: fadd(t2, zz[20+d]) <= 36} (monotone predicate -> binary ascent;
    // zz exactly symmetric about 20 since (-x)*(-x)==x*x).
    for (int r = tid; r < NROWS; r += THREADS) {
        const int i = div41(r);
        const int j = r - i * NXG;
        const float t2 = __fadd_rn(xs2[i], ys2[j]);
        int d = -1;
        #pragma unroll
        for (int step = 16; step; step >>= 1) {
            int nd = d + step;
            if (nd <= 20 && __fadd_rn(t2, zz[20 + nd]) <= 36.0f) d = nd;
        }
        rowlo[r] = (uint8_t)(20 - d);      // 21 when row entirely outside sphere
    }
    __syncthreads();

    // ---------------- Phase 1: per-warp double-buffered stream + row max -----
    for (int c = 0; c < nch; c++) {
        if (c + 1 < nch) issue_chunk(c + 1);

        // Wait chunk c: stage (c&1), parity flips per reuse of that stage.
        MBAR_WAIT(mb0 + (uint32_t)(c & 1) * 8u, (uint32_t)((c >> 1) & 1));
        if (tailflag) { CP_WAIT0(); tailflag = 0; }
        __syncwarp();

        // Thread-pair per row: even lane ks [0,21), odd [21,41). MAX ONLY.
        const int row0  = rstart + c * WCH;
        const int nrows = min(WCH, rend - row0);
        const int sft   = (int)((base + (size_t)row0 * NXG) & 3);
        const int lr    = lane >> 1;                 // 0..15
        const int half  = lane & 1;
        const int r     = min(row0 + lr, NROWS - 1);
        const int klo   = (int)rowlo[r];
        const int khi   = 40 - klo;
        const int kb    = half * 21;
        const float* rowp = wb[c & 1] + sft + lr * NXG + kb;

        float best = NEGF;
        #pragma unroll
        for (int kk = 0; kk < 21; kk++) {
            const int k = kb + kk;                   // k=41 slot: khi<41 -> invalid
            const float v = rowp[kk];                // in-bounds via WBUF slack
            if (k >= klo && k <= khi) best = fmaxf(best, v);
        }
        const float vo = __shfl_down_sync(0xffffffffu, best, 1);
        if (half == 0 && lr < nrows)
            rowmax[row0 + lr] = fmaxf(best, vo);
        __syncwarp();   // all lanes done with buf[c&1] before it is refilled
    }
    __syncthreads();    // all warps' rowmax complete

    // ---------------- Phase 2: K iterations of argmax + local NMS ------------
    int pk_i[KP], pk_j[KP], pk_k[KP];
    int npk = 0;   // replicated across threads (derived from shared data)

    for (int it = 0; it < KP; it++) {
        // Block argmax over rowmax[0..1680], first-occurrence tie-break.
        float bv = -__int_as_float(0x7f800000);
        int   br = 0x7fffffff;
        for (int r = tid; r < NROWS; r += THREADS) {
            float v = rowmax[r];
            if (v > bv) { bv = v; br = r; }        // r ascending: ties keep earlier
        }
        #pragma unroll
        for (int off = 16; off; off >>= 1) {
            float ov = __shfl_xor_sync(0xffffffffu, bv, off);
            int   orr = __shfl_xor_sync(0xffffffffu, br, off);
            if (ov > bv || (ov == bv && orr < br)) { bv = ov; br = orr; }
        }
        if (lane == 0) { swv[w] = bv; swr[w] = br; }
        __syncthreads();
        if (w == 0) {
            float v = (lane < NWARP) ? swv[lane] : -__int_as_float(0x7f800000);
            int   r = (lane < NWARP) ? swr[lane] : 0x7fffffff;
            #pragma unroll
            for (int off = 4; off; off >>= 1) {
                float ov = __shfl_xor_sync(0xffffffffu, v, off);
                int   orr = __shfl_xor_sync(0xffffffffu, r, off);
                if (ov > v || (ov == v && orr < r)) { v = ov; r = orr; }
            }
            if (lane == 0) *s_pick = r;
        }
        __syncthreads();

        const int   pr  = *s_pick;
        const float sc  = rowmax[pr];
        const int   pi  = div41(pr);
        const int   pj  = pr - pi * NXG;
        const bool  valid = sc > VTH;

        // Warp 0 recomputes argmax-k of the picked row (mask + suppression by
        // the npk peaks picked so far; first-k tie-break). L2-hot loads.
        if (w == 0) {
            const float t2 = __fadd_rn(xs2[pi], ys2[pj]);
            const float* rowg = density + base + (size_t)pr * NXG;
            bool in0 = 0 < npk && abs(pi - pk_i[0]) <= SEP && abs(pj - pk_j[0]) <= SEP;
            bool in1 = 1 < npk && abs(pi - pk_i[1]) <= SEP && abs(pj - pk_j[1]) <= SEP;
            bool in2 = 2 < npk && abs(pi - pk_i[2]) <= SEP && abs(pj - pk_j[2]) <= SEP;

            float bvv = NEGF; int bkk = lane;
            {
                const int k = lane;
                bool sup = (__fadd_rn(t2, zz[k]) > 36.0f);
                if (in0 && abs(k - pk_k[0]) <= SEP) sup = true;
                if (in1 && abs(k - pk_k[1]) <= SEP) sup = true;
                if (in2 && abs(k - pk_k[2]) <= SEP) sup = true;
                if (!sup) bvv = __ldg(&rowg[k]);
            }
            const int k2 = lane + 32;
            if (k2 < NXG) {
                bool sup = (__fadd_rn(t2, zz[k2]) > 36.0f);
                if (in0 && abs(k2 - pk_k[0]) <= SEP) sup = true;
                if (in1 && abs(k2 - pk_k[1]) <= SEP) sup = true;
                if (in2 && abs(k2 - pk_k[2]) <= SEP) sup = true;
                if (!sup) {
                    const float v2 = __ldg(&rowg[k2]);
                    if (v2 > bvv) { bvv = v2; bkk = k2; }
                }
            }
            #pragma unroll
            for (int off = 16; off; off >>= 1) {
                const float ov = __shfl_xor_sync(0xffffffffu, bvv, off);
                const int   ok = __shfl_xor_sync(0xffffffffu, bkk, off);
                if (ov > bvv || (ov == bvv && ok < bkk)) { bvv = ov; bkk = ok; }
            }
            if (lane == 0) *s_pkk = bkk;
        }
        __syncthreads();

        const int pkk = *s_pkk;
        if (tid == 0) {
            s_ps[it] = sc;
            s_pg[it] = pr * NXG + pkk;
            s_pv[it] = valid ? 1 : 0;
        }
        if (valid) { pk_i[npk] = pi; pk_j[npk] = pj; pk_k[npk] = pkk; npk++; }
        __syncthreads();   // everyone done reading rowmax before rewrite

        if (it == KP - 1) break;

        // Recompute rows intersecting the new peak's Chebyshev ball, applying
        // suppression from ALL picked-so-far peaks. Max value only.
        if (valid) {
            const int i0 = max(pi - SEP, 0), i1 = min(pi + SEP, NXG - 1);
            const int j0 = max(pj - SEP, 0), j1 = min(pj + SEP, NXG - 1);
            const int nj = j1 - j0 + 1;
            const int nr = (i1 - i0 + 1) * nj;
            if (tid < nr) {
                const int i = i0 + tid / nj;
                const int j = j0 + tid % nj;
                const int r = i * NXG + j;
                const float t2 = __fadd_rn(xs2[i], ys2[j]);
                const float* rowg = density + base + (size_t)r * NXG;

                bool in0 = 0 < npk && abs(i - pk_i[0]) <= SEP && abs(j - pk_j[0]) <= SEP;
                bool in1 = 1 < npk && abs(i - pk_i[1]) <= SEP && abs(j - pk_j[1]) <= SEP;
                bool in2 = 2 < npk && abs(i - pk_i[2]) <= SEP && abs(j - pk_j[2]) <= SEP;

                float best = NEGF;
                #pragma unroll
                for (int k = 0; k < NXG; k++) {
                    const float dv = __ldg(&rowg[k]);   // unconditional: enables MLP
                    bool sup = (__fadd_rn(t2, zz[k]) > 36.0f);
                    if (in0 && abs(k - pk_k[0]) <= SEP) sup = true;
                    if (in1 && abs(k - pk_k[1]) <= SEP) sup = true;
                    if (in2 && abs(k - pk_k[2]) <= SEP) sup = true;
                    best = fmaxf(best, sup ? NEGF : dv);
                }
                rowmax[r] = best;
            }
        }
        __syncthreads();
    }

    // ---------------- Epilogue: transform + write outputs --------------------
    // Output layout: coords_local [NC,K,3] | coords_global [NC,K,3] |
    //                scores [NC,K] | mask [NC,K]  (all float32)
    if (tid < KP) {
        const int kk = tid;
        const int n  = p / C;
        const int NC = gridDim.x;

        const float sc    = s_ps[kk];
        const bool  valid = (s_pv[kk] != 0);
        const int   g     = s_pg[kk];

        float x = 0.f, y = 0.f, z = 0.f;
        if (valid) {
            x = grid_xyz[3 * g + 0];
            y = grid_xyz[3 * g + 1];
            z = grid_xyz[3 * g + 2];
        }
        const float nm = node_mask[n];
        const float* R = Rmats + (size_t)n * 9;
        const float* t = tpos  + (size_t)n * 3;
        const float gx = R[0] * x + R[1] * y + R[2] * z + t[0];
        const float gy = R[3] * x + R[4] * y + R[5] * z + t[1];
        const float gz = R[6] * x + R[7] * y + R[8] * z + t[2];

        float* CL = out;
        float* CG = out + (size_t)NC * KP * 3;
        float* SC = out + (size_t)NC * KP * 6;
        float* MS = SC  + (size_t)NC * KP;

        const size_t o3 = ((size_t)p * KP + kk) * 3;
        CL[o3 + 0] = x * nm;  CL[o3 + 1] = y * nm;  CL[o3 + 2] = z * nm;
        CG[o3 + 0] = gx * nm; CG[o3 + 1] = gy * nm; CG[o3 + 2] = gz * nm;
        SC[(size_t)p * KP + kk] = (valid ? sc : NEGF) * nm;
        MS[(size_t)p * KP + kk] = (valid && nm != 0.0f) ? 1.0f : 0.0f;
    }
}

extern "C" void kernel_launch(void* const* d_in, const int* in_sizes, int n_in,
                              void* d_out, int out_size)
{
    // Input order per reference setup_inputs():
    // 0: density [B,N,C,G] f32   1: grid_xyz [G,3] f32   2: sphere_mask (unused)
    // 3: coords_int (unused)     4: Rmats [B,N,3,3] f32  5: tpos [B,N,3] f32
    // 6: node_mask [B,N] f32
    const float* density   = (const float*)d_in[0];
    const float* grid_xyz  = (const float*)d_in[1];
    const float* Rmats     = (const float*)d_in[4];
    const float* tposp     = (const float*)d_in[5];
    const float* node_mask = (const float*)d_in[6];
    float* out = (float*)d_out;

    const int NC = in_sizes[0] / GVOX;      // B*N*C = 512
    const int N  = in_sizes[4] / 9;         // B*N   = 128
    const int C  = NC / N;                  // 4
    (void)n_in; (void)out_size;

    static int smem_set = 0;
    if (!smem_set) {
        cudaFuncSetAttribute(fused_peaks_kernel,
                             cudaFuncAttributeMaxDynamicSharedMemorySize, SM_TOTAL);
        smem_set = 1;
    }
    fused_peaks_kernel<<<NC, THREADS, SM_TOTAL>>>(density, grid_xyz, Rmats, tposp,
                                                  node_mask, out, C);
}

// round 9
// speedup vs baseline: 1.0815x; 1.0815x over previous
#include <cuda_runtime.h>
#include <stdint.h>

// Problem constants (fixed by the reference: NX=41, r_max=6.0, voxel=0.3, K=4, min_sep=3)
#define NXG    41
#define NROWS  (NXG * NXG)       // 1681 rows of 41 voxels
#define GVOX   (NXG * NXG * NXG) // 68921
#define KP     4
#define SEP    3
#define NEGF   (-1.0e9f)
#define VTH    (-1.0e8f)

#define THREADS 256
#define NWARP   8
#define CHROWS  128                            // rows per block chunk
#define NCHUNK  ((NROWS + CHROWS - 1) / CHROWS) // 14
#define CHBUF   (CHROWS * NXG + 8)             // 5256 floats = 21024 B (mult of 16)

// Shared-memory layout (bytes); buffers 16B-aligned.
#define SM_BUF    0                                   // 2 * 21024 = 42048
#define SM_MBAR   (SM_BUF + 2 * CHBUF * 4)            // 16
#define SM_ROWMAX (SM_MBAR + 16)                      // 6724
#define SM_ROWLO  (SM_ROWMAX + NROWS * 4)             // 1684
#define SM_XS2    (SM_ROWLO + 1684)                   // 168
#define SM_YS2    (SM_XS2 + 168)
#define SM_ZZ     (SM_YS2 + 168)
#define SM_SWV    (SM_ZZ + 168)
#define SM_SWR    (SM_SWV + 32)
#define SM_PICK   (SM_SWR + 32)
#define SM_PKK    (SM_PICK + 4)
#define SM_PS     (SM_PKK + 4)
#define SM_PG     (SM_PS + 16)
#define SM_PV     (SM_PG + 16)
#define SM_TOTAL  (SM_PV + 16 + 32)                   // ~51.2 KB -> 4 CTAs/SM

#define CP_ASYNC_4(dst, src) \
    asm volatile("cp.async.ca.shared.global [%0], [%1], 4;"  :: "r"(dst), "l"(src) : "memory")
#define CP_COMMIT()  asm volatile("cp.async.commit_group;" ::: "memory")
#define CP_WAIT0()   asm volatile("cp.async.wait_group 0;" ::: "memory")

#define MBAR_INIT(mbar, cnt) \
    asm volatile("mbarrier.init.shared.b64 [%0], %1;" :: "r"(mbar), "r"(cnt) : "memory")
#define MBAR_EXPECT_TX(mbar, bytes) \
    asm volatile("mbarrier.arrive.expect_tx.shared.b64 _, [%0], %1;" :: "r"(mbar), "r"(bytes) : "memory")
#define FENCE_PROXY_ASYNC() asm volatile("fence.proxy.async.shared::cta;" ::: "memory")

#define MBAR_WAIT(mbar, par) do {                                              \
    uint32_t _m = (mbar); uint32_t _p = (par); uint32_t _d;                    \
    asm volatile("{\n\t.reg .pred p;\n\t"                                      \
        "mbarrier.try_wait.parity.acquire.cta.shared::cta.b64 p, [%1], %2;\n\t"\
        "selp.b32 %0, 1, 0, p;\n\t}"                                           \
        : "=r"(_d) : "r"(_m), "r"(_p) : "memory");                             \
    if (!_d) {                                                                 \
        asm volatile("{\n\t.reg .pred P1;\n\t"                                 \
            "WL_%=:\n\t"                                                       \
            "mbarrier.try_wait.parity.acquire.cta.shared::cta.b64 P1, [%0], %1, 0x989680;\n\t" \
            "@P1 bra.uni WD_%=;\n\t"                                           \
            "bra.uni WL_%=;\n\t"                                               \
            "WD_%=:\n\t}"                                                      \
            :: "r"(_m), "r"(_p) : "memory");                                   \
    }                                                                          \
} while (0)

#define BULK_LD(dst, src, bytes, mbar) \
    asm volatile("cp.async.bulk.shared::cluster.global.mbarrier::complete_tx::bytes " \
                 "[%0], [%1], %2, [%3];" \
                 :: "r"(dst), "l"(src), "r"(bytes), "r"(mbar) : "memory")

static __device__ __forceinline__ uint32_t smem_u32(const void* p) {
    return (uint32_t)__cvta_generic_to_shared(p);
}

// Exact floor(r/41) for 0 <= r < 53773.
static __device__ __forceinline__ int div41(int r) {
    return (int)(((unsigned)r * 51151u) >> 21);
}

// ---------------------------------------------------------------------------
// Fully fused: block-wide 21KB TMA bulk chunks (8x fewer/bigger requests than
// R7/R8 warp chunks -> amortize per-request service cost), double-buffered.
// Phase-1 computes per-row MAX only; picked-row argmax-k recomputed in phase 2.
// One CTA per (n,c) problem, 256 threads = 128 rows x pair-per-row per chunk.
__global__ __launch_bounds__(THREADS, 4)
void fused_peaks_kernel(const float* __restrict__ density,
                        const float* __restrict__ grid_xyz,
                        const float* __restrict__ Rmats,
                        const float* __restrict__ tpos,
                        const float* __restrict__ node_mask,
                        float* __restrict__ out,
                        int C)
{
    extern __shared__ char smem[];
    float*   buf0   = (float*)(smem + SM_BUF);
    float*   buf1   = buf0 + CHBUF;
    float*   rowmax = (float*)(smem + SM_ROWMAX);
    uint8_t* rowlo  = (uint8_t*)(smem + SM_ROWLO);
    float*   xs2    = (float*)(smem + SM_XS2);
    float*   ys2    = (float*)(smem + SM_YS2);
    float*   zz     = (float*)(smem + SM_ZZ);
    float*   swv    = (float*)(smem + SM_SWV);
    int*     swr    = (int*)(smem + SM_SWR);
    int*     s_pick = (int*)(smem + SM_PICK);
    int*     s_pkk  = (int*)(smem + SM_PKK);
    float*   s_ps   = (float*)(smem + SM_PS);
    int*     s_pg   = (int*)(smem + SM_PG);
    int*     s_pv   = (int*)(smem + SM_PV);

    const int tid  = threadIdx.x;
    const int lane = tid & 31;
    const int w    = tid >> 5;
    const int p    = blockIdx.x;
    const size_t base    = (size_t)p * GVOX;        // base % 4 == p % 4
    const size_t total_f = (size_t)gridDim.x * GVOX;
    const uint32_t mb = smem_u32(smem + SM_MBAR);
    const int sft = (int)(base & 3);                // same for every chunk (CHROWS*NXG%4==0)

    // Issue chunk c's 21KB bulk copy (tid 0 path + rare tail by tids<4).
    // Returns whether a cp.async tail group was used (uniform across threads).
    auto issue_chunk = [&](int c) -> bool {
        const int row0  = c * CHROWS;
        const int nrows = min(CHROWS, NROWS - row0);
        const size_t need_start = base + (size_t)row0 * NXG;
        const size_t srcA = need_start & ~(size_t)3;          // 16B-aligned float idx
        size_t endA = (need_start + (size_t)nrows * NXG + 3) & ~(size_t)3;
        bool tail = false;
        if (endA > total_f) { endA -= 4; tail = true; }       // never when NC%4==0
        const uint32_t bytes = (uint32_t)(endA - srcA) * 4u;
        const uint32_t dstb  = smem_u32((c & 1) ? buf1 : buf0);
        const uint32_t mbar  = mb + (uint32_t)(c & 1) * 8u;
        if (tid == 0) {
            MBAR_EXPECT_TX(mbar, bytes);
            BULK_LD(dstb, density + srcA, bytes, mbar);
        }
        if (tail) {
            const size_t need_end = need_start + (size_t)nrows * NXG;
            const int nrem = (int)(need_end - endA);          // 1..4
            if (tid < nrem)
                CP_ASYNC_4(dstb + (uint32_t)(endA - srcA + tid) * 4u,
                           density + endA + tid);
            CP_COMMIT();
        }
        return tail;
    };

    if (tid == 0) {
        MBAR_INIT(mb, 1);
        MBAR_INIT(mb + 8, 1);
        FENCE_PROXY_ASYNC();
    }
    __syncthreads();          // mbarriers initialized before anyone waits
    bool tail0 = issue_chunk(0);   // overlaps table building below

    // Per-axis squared coords from the ACTUAL grid_xyz input.
    // Sphere test (s<=36.0f) is bit-equivalent to sqrtf(s)<=6.0f under RN.
    if (tid < NXG) {
        float x = grid_xyz[3 * (tid * NXG * NXG) + 0];
        float y = grid_xyz[3 * (tid * NXG) + 1];
        float z = grid_xyz[3 * tid + 2];
        xs2[tid] = __fmul_rn(x, x);
        ys2[tid] = __fmul_rn(y, y);
        zz[tid]  = __fmul_rn(z, z);
    }
    __syncthreads();

    // Per-row valid interval: valid ks = [klo, 40-klo], klo = 20-d where
    // d = max{d: fadd(t2, zz[20+d]) <= 36} (monotone predicate -> binary ascent;
    // zz exactly symmetric about 20 since (-x)*(-x)==x*x).
    for (int r = tid; r < NROWS; r += THREADS) {
        const int i = div41(r);
        const int j = r - i * NXG;
        const float t2 = __fadd_rn(xs2[i], ys2[j]);
        int d = -1;
        #pragma unroll
        for (int step = 16; step; step >>= 1) {
            int nd = d + step;
            if (nd <= 20 && __fadd_rn(t2, zz[20 + nd]) <= 36.0f) d = nd;
        }
        rowlo[r] = (uint8_t)(20 - d);      // 21 when row entirely outside sphere
    }
    __syncthreads();

    // ---------------- Phase 1: double-buffered 21KB chunks + row max ---------
    bool tail_cur = tail0;
    for (int c = 0; c < NCHUNK; c++) {
        bool tail_next = false;
        if (c + 1 < NCHUNK) tail_next = issue_chunk(c + 1);

        // Wait chunk c: stage (c&1), parity flips per reuse of that stage.
        MBAR_WAIT(mb + (uint32_t)(c & 1) * 8u, (uint32_t)((c >> 1) & 1));
        if (tail_cur) { CP_WAIT0(); __syncthreads(); }
        tail_cur = tail_next;

        // Pair-per-row: even tid ks [0,21), odd [21,41). MAX ONLY.
        const int row0  = c * CHROWS;
        const int nrows = min(CHROWS, NROWS - row0);
        const int lr    = tid >> 1;                  // 0..127
        const int half  = tid & 1;
        const int r     = min(row0 + lr, NROWS - 1);
        const int klo   = (int)rowlo[r];
        const int khi   = 40 - klo;
        const int kb    = half * 21;
        const float* rowp = ((c & 1) ? buf1 : buf0) + sft + lr * NXG + kb;

        float best = NEGF;
        #pragma unroll
        for (int kk = 0; kk < 21; kk++) {
            const int k = kb + kk;                   // k=41 slot: khi<41 -> invalid
            const float v = rowp[kk];                // in-bounds via CHBUF slack
            if (k >= klo && k <= khi) best = fmaxf(best, v);
        }
        const float vo = __shfl_down_sync(0xffffffffu, best, 1);
        if (half == 0 && lr < nrows)
            rowmax[row0 + lr] = fmaxf(best, vo);
        __syncthreads();   // all threads done with buffer (c&1) before refill
    }

    // ---------------- Phase 2: K iterations of argmax + local NMS ------------
    int pk_i[KP], pk_j[KP], pk_k[KP];
    int npk = 0;   // replicated across threads (derived from shared data)

    for (int it = 0; it < KP; it++) {
        // Block argmax over rowmax[0..1680], first-occurrence tie-break.
        float bv = -__int_as_float(0x7f800000);
        int   br = 0x7fffffff;
        for (int r = tid; r < NROWS; r += THREADS) {
            float v = rowmax[r];
            if (v > bv) { bv = v; br = r; }        // r ascending: ties keep earlier
        }
        #pragma unroll
        for (int off = 16; off; off >>= 1) {
            float ov = __shfl_xor_sync(0xffffffffu, bv, off);
            int   orr = __shfl_xor_sync(0xffffffffu, br, off);
            if (ov > bv || (ov == bv && orr < br)) { bv = ov; br = orr; }
        }
        if (lane == 0) { swv[w] = bv; swr[w] = br; }
        __syncthreads();
        if (w == 0) {
            float v = (lane < NWARP) ? swv[lane] : -__int_as_float(0x7f800000);
            int   r = (lane < NWARP) ? swr[lane] : 0x7fffffff;
            #pragma unroll
            for (int off = 4; off; off >>= 1) {
                float ov = __shfl_xor_sync(0xffffffffu, v, off);
                int   orr = __shfl_xor_sync(0xffffffffu, r, off);
                if (ov > v || (ov == v && orr < r)) { v = ov; r = orr; }
            }
            if (lane == 0) *s_pick = r;
        }
        __syncthreads();

        const int   pr  = *s_pick;
        const float sc  = rowmax[pr];
        const int   pi  = div41(pr);
        const int   pj  = pr - pi * NXG;
        const bool  valid = sc > VTH;

        // Warp 0 recomputes argmax-k of the picked row (mask + suppression by
        // the npk peaks picked so far; first-k tie-break). L2-hot loads.
        if (w == 0) {
            const float t2 = __fadd_rn(xs2[pi], ys2[pj]);
            const float* rowg = density + base + (size_t)pr * NXG;
            bool in0 = 0 < npk && abs(pi - pk_i[0]) <= SEP && abs(pj - pk_j[0]) <= SEP;
            bool in1 = 1 < npk && abs(pi - pk_i[1]) <= SEP && abs(pj - pk_j[1]) <= SEP;
            bool in2 = 2 < npk && abs(pi - pk_i[2]) <= SEP && abs(pj - pk_j[2]) <= SEP;

            float bvv = NEGF; int bkk = lane;
            {
                const int k = lane;
                bool sup = (__fadd_rn(t2, zz[k]) > 36.0f);
                if (in0 && abs(k - pk_k[0]) <= SEP) sup = true;
                if (in1 && abs(k - pk_k[1]) <= SEP) sup = true;
                if (in2 && abs(k - pk_k[2]) <= SEP) sup = true;
                if (!sup) bvv = __ldg(&rowg[k]);
            }
            const int k2 = lane + 32;
            if (k2 < NXG) {
                bool sup = (__fadd_rn(t2, zz[k2]) > 36.0f);
                if (in0 && abs(k2 - pk_k[0]) <= SEP) sup = true;
                if (in1 && abs(k2 - pk_k[1]) <= SEP) sup = true;
                if (in2 && abs(k2 - pk_k[2]) <= SEP) sup = true;
                if (!sup) {
                    const float v2 = __ldg(&rowg[k2]);
                    if (v2 > bvv) { bvv = v2; bkk = k2; }
                }
            }
            #pragma unroll
            for (int off = 16; off; off >>= 1) {
                const float ov = __shfl_xor_sync(0xffffffffu, bvv, off);
                const int   ok = __shfl_xor_sync(0xffffffffu, bkk, off);
                if (ov > bvv || (ov == bvv && ok < bkk)) { bvv = ov; bkk = ok; }
            }
            if (lane == 0) *s_pkk = bkk;
        }
        __syncthreads();

        const int pkk = *s_pkk;
        if (tid == 0) {
            s_ps[it] = sc;
            s_pg[it] = pr * NXG + pkk;
            s_pv[it] = valid ? 1 : 0;
        }
        if (valid) { pk_i[npk] = pi; pk_j[npk] = pj; pk_k[npk] = pkk; npk++; }
        __syncthreads();   // everyone done reading rowmax before rewrite

        if (it == KP - 1) break;

        // Recompute rows intersecting the new peak's Chebyshev ball, applying
        // suppression from ALL picked-so-far peaks. Max value only.
        if (valid) {
            const int i0 = max(pi - SEP, 0), i1 = min(pi + SEP, NXG - 1);
            const int j0 = max(pj - SEP, 0), j1 = min(pj + SEP, NXG - 1);
            const int nj = j1 - j0 + 1;
            const int nr = (i1 - i0 + 1) * nj;
            if (tid < nr) {
                const int i = i0 + tid / nj;
                const int j = j0 + tid % nj;
                const int r = i * NXG + j;
                const float t2 = __fadd_rn(xs2[i], ys2[j]);
                const float* rowg = density + base + (size_t)r * NXG;

                bool in0 = 0 < npk && abs(i - pk_i[0]) <= SEP && abs(j - pk_j[0]) <= SEP;
                bool in1 = 1 < npk && abs(i - pk_i[1]) <= SEP && abs(j - pk_j[1]) <= SEP;
                bool in2 = 2 < npk && abs(i - pk_i[2]) <= SEP && abs(j - pk_j[2]) <= SEP;

                float best = NEGF;
                #pragma unroll
                for (int k = 0; k < NXG; k++) {
                    const float dv = __ldg(&rowg[k]);   // unconditional: enables MLP
                    bool sup = (__fadd_rn(t2, zz[k]) > 36.0f);
                    if (in0 && abs(k - pk_k[0]) <= SEP) sup = true;
                    if (in1 && abs(k - pk_k[1]) <= SEP) sup = true;
                    if (in2 && abs(k - pk_k[2]) <= SEP) sup = true;
                    best = fmaxf(best, sup ? NEGF : dv);
                }
                rowmax[r] = best;
            }
        }
        __syncthreads();
    }

    // ---------------- Epilogue: transform + write outputs --------------------
    // Output layout: coords_local [NC,K,3] | coords_global [NC,K,3] |
    //                scores [NC,K] | mask [NC,K]  (all float32)
    if (tid < KP) {
        const int kk = tid;
        const int n  = p / C;
        const int NC = gridDim.x;

        const float sc    = s_ps[kk];
        const bool  valid = (s_pv[kk] != 0);
        const int   g     = s_pg[kk];

        float x = 0.f, y = 0.f, z = 0.f;
        if (valid) {
            x = grid_xyz[3 * g + 0];
            y = grid_xyz[3 * g + 1];
            z = grid_xyz[3 * g + 2];
        }
        const float nm = node_mask[n];
        const float* R = Rmats + (size_t)n * 9;
        const float* t = tpos  + (size_t)n * 3;
        const float gx = R[0] * x + R[1] * y + R[2] * z + t[0];
        const float gy = R[3] * x + R[4] * y + R[5] * z + t[1];
        const float gz = R[6] * x + R[7] * y + R[8] * z + t[2];

        float* CL = out;
        float* CG = out + (size_t)NC * KP * 3;
        float* SC = out + (size_t)NC * KP * 6;
        float* MS = SC  + (size_t)NC * KP;

        const size_t o3 = ((size_t)p * KP + kk) * 3;
        CL[o3 + 0] = x * nm;  CL[o3 + 1] = y * nm;  CL[o3 + 2] = z * nm;
        CG[o3 + 0] = gx * nm; CG[o3 + 1] = gy * nm; CG[o3 + 2] = gz * nm;
        SC[(size_t)p * KP + kk] = (valid ? sc : NEGF) * nm;
        MS[(size_t)p * KP + kk] = (valid && nm != 0.0f) ? 1.0f : 0.0f;
    }
}

extern "C" void kernel_launch(void* const* d_in, const int* in_sizes, int n_in,
                              void* d_out, int out_size)
{
    // Input order per reference setup_inputs():
    // 0: density [B,N,C,G] f32   1: grid_xyz [G,3] f32   2: sphere_mask (unused)
    // 3: coords_int (unused)     4: Rmats [B,N,3,3] f32  5: tpos [B,N,3] f32
    // 6: node_mask [B,N] f32
    const float* density   = (const float*)d_in[0];
    const float* grid_xyz  = (const float*)d_in[1];
    const float* Rmats     = (const float*)d_in[4];
    const float* tposp     = (const float*)d_in[5];
    const float* node_mask = (const float*)d_in[6];
    float* out = (float*)d_out;

    const int NC = in_sizes[0] / GVOX;      // B*N*C = 512
    const int N  = in_sizes[4] / 9;         // B*N   = 128
    const int C  = NC / N;                  // 4
    (void)n_in; (void)out_size;

    static int smem_set = 0;
    if (!smem_set) {
        cudaFuncSetAttribute(fused_peaks_kernel,
                             cudaFuncAttributeMaxDynamicSharedMemorySize, SM_TOTAL);
        smem_set = 1;
    }
    fused_peaks_kernel<<<NC, THREADS, SM_TOTAL>>>(density, grid_xyz, Rmats, tposp,
                                                  node_mask, out, C);
}